// round 1
// baseline (speedup 1.0000x reference)
#include <cuda_runtime.h>

// ---------------- problem constants ----------------
#define BN 2
#define NN 16384
#define DD 3
#define FD 128
#define HD 128
#define KK 4

#define HT_STRIDE 132   // padded row stride for the transposed h tile (feature-major)

// ---------------- device scratch (no allocations allowed) ----------------
__device__ __align__(256) float g_gW0[BN * NN * HD];          // feat @ W0[3:] + b0   (16 MB)
__device__ __align__(256) float g_grad[BN * NN * KK * DD];    // per-(n,k) grad_pred (1.5 MB)

// ---------------- shared 8x8 microtile GEMM over a 128x128x128 tile ----------------
// shT: [128 k][HT_STRIDE rows]  (feature-major / transposed h)
// shW: [128 k][128 cols]
__device__ __forceinline__ void gemm_tile(const float* __restrict__ shT,
                                          const float* __restrict__ shW,
                                          int r0, int c0, float acc[8][8])
{
#pragma unroll
    for (int i = 0; i < 8; ++i)
#pragma unroll
        for (int j = 0; j < 8; ++j) acc[i][j] = 0.f;

#pragma unroll 4
    for (int k = 0; k < 128; ++k) {
        float4 a0 = *(const float4*)(shT + k * HT_STRIDE + r0);
        float4 a1 = *(const float4*)(shT + k * HT_STRIDE + r0 + 4);
        float4 w0 = *(const float4*)(shW + k * 128 + c0);
        float4 w1 = *(const float4*)(shW + k * 128 + c0 + 4);
        float a[8] = {a0.x, a0.y, a0.z, a0.w, a1.x, a1.y, a1.z, a1.w};
        float w[8] = {w0.x, w0.y, w0.z, w0.w, w1.x, w1.y, w1.z, w1.w};
#pragma unroll
        for (int i = 0; i < 8; ++i)
#pragma unroll
            for (int j = 0; j < 8; ++j)
                acc[i][j] = fmaf(a[i], w[j], acc[i][j]);
    }
}

// ---------------- precompute: gW0 = (relu(pcl@Wf1+bf1) @ Wf2 + bf2) @ W0[3:] + b0 ----------------
// also initializes out = pcl_noisy. One block = 128 points, 256 threads.
__global__ __launch_bounds__(256, 1)
void precompute_kernel(const float* __restrict__ pcl,
                       const float* __restrict__ Wf1, const float* __restrict__ bf1,
                       const float* __restrict__ Wf2, const float* __restrict__ bf2,
                       const float* __restrict__ W0,  const float* __restrict__ b0,
                       float* __restrict__ out)
{
    extern __shared__ float sm[];
    float* shT = sm;                       // 128 * HT_STRIDE
    float* shW = sm + 128 * HT_STRIDE;     // 128 * 128

    const int t  = threadIdx.x;
    const int b  = blockIdx.y;
    const int n0 = blockIdx.x * 128;
    const float* pclb = pcl + ((size_t)b * NN + n0) * 3;
    float* outb = out + ((size_t)b * NN + n0) * 3;

    // init output = pcl_noisy
    for (int i = t; i < 128 * 3; i += 256) outb[i] = pclb[i];

    // h1 = relu(pcl @ Wf1 + bf1), stored feature-major
    {
        int r = t & 127;
        int half = t >> 7;
        float x0 = pclb[r * 3 + 0], x1 = pclb[r * 3 + 1], x2 = pclb[r * 3 + 2];
        for (int j = half; j < 128; j += 2) {
            float v = fmaf(x0, Wf1[j], fmaf(x1, Wf1[128 + j], fmaf(x2, Wf1[256 + j], bf1[j])));
            shT[j * HT_STRIDE + r] = fmaxf(v, 0.f);
        }
    }

    const int ty = t >> 4, tx = t & 15;
    const int r0 = ty * 8, c0 = tx * 8;
    float acc[8][8];

    // GEMM1: feat = h1 @ Wf2 + bf2  (no relu)
    __syncthreads();
    for (int i = t * 4; i < 128 * 128; i += 1024)
        *(float4*)(shW + i) = *(const float4*)(Wf2 + i);
    __syncthreads();
    gemm_tile(shT, shW, r0, c0, acc);
    __syncthreads();
    {
        float bv[8];
#pragma unroll
        for (int j = 0; j < 8; ++j) bv[j] = bf2[c0 + j];
#pragma unroll
        for (int i = 0; i < 8; ++i)
#pragma unroll
            for (int j = 0; j < 8; ++j)
                shT[(c0 + j) * HT_STRIDE + (r0 + i)] = acc[i][j] + bv[j];
    }

    // GEMM2: gW0 = feat @ W0[3:] + b0
    __syncthreads();
    for (int i = t * 4; i < 128 * 128; i += 1024)
        *(float4*)(shW + i) = *(const float4*)(W0 + 3 * 128 + i);
    __syncthreads();
    gemm_tile(shT, shW, r0, c0, acc);
    {
        float bv[8];
#pragma unroll
        for (int j = 0; j < 8; ++j) bv[j] = b0[c0 + j];
        float* gb = g_gW0 + ((size_t)b * NN + n0) * 128;
#pragma unroll
        for (int i = 0; i < 8; ++i) {
            float4 v0 = make_float4(acc[i][0] + bv[0], acc[i][1] + bv[1],
                                    acc[i][2] + bv[2], acc[i][3] + bv[3]);
            float4 v1 = make_float4(acc[i][4] + bv[4], acc[i][5] + bv[5],
                                    acc[i][6] + bv[6], acc[i][7] + bv[7]);
            *(float4*)(gb + (size_t)(r0 + i) * 128 + c0)     = v0;
            *(float4*)(gb + (size_t)(r0 + i) * 128 + c0 + 4) = v1;
        }
    }
}

// ---------------- per-step score net: grads for 32 points x 4 neighbors = 128 rows/block ----------------
__global__ __launch_bounds__(256, 1)
void grad_kernel(const float* __restrict__ pcl_noisy, const float* __restrict__ pcl_cur,
                 const float* __restrict__ W0, const float* __restrict__ Wb,
                 const float* __restrict__ bb, const float* __restrict__ Wo,
                 const float* __restrict__ bo)
{
    extern __shared__ float sm[];
    float* shT  = sm;                        // 128 * HT_STRIDE   (h, feature-major)
    float* shW  = shT + 128 * HT_STRIDE;     // 128 * 128         (current weight tile)
    float* shC  = shW + 128 * 128;           // 3 * 128  centered, layout [d*128 + r]
    float* shW0 = shC + 3 * 128;             // 3 * 128  first 3 rows of W0
    float* shWo = shW0 + 3 * 128;            // 128 * 3

    const int t  = threadIdx.x;
    const int b  = blockIdx.y;
    const int n0 = blockIdx.x * 32;

    for (int i = t; i < 384; i += 256) { shW0[i] = W0[i]; shWo[i] = Wo[i]; }

    if (t < 128) {
        int r = t, p = r >> 2, q = r & 3;
        int n = n0 + p;
        int m = n + q - 2;
        m = m < 0 ? 0 : (m > NN - 1 ? NN - 1 : m);
        const float* pc = pcl_cur  + ((size_t)b * NN + m) * 3;
        const float* pn = pcl_noisy + ((size_t)b * NN + n) * 3;
        shC[r]       = pc[0] - pn[0];
        shC[128 + r] = pc[1] - pn[1];
        shC[256 + r] = pc[2] - pn[2];
    }
    __syncthreads();

    // h0 = relu(centered @ W0[:3] + gW0)
    {
        const float* gW0b = g_gW0 + ((size_t)b * NN + n0) * 128;
        int r = t & 127, half = t >> 7;
        float c0v = shC[r], c1v = shC[128 + r], c2v = shC[256 + r];
        const float* gw = gW0b + (size_t)(r >> 2) * 128;
        for (int j = half; j < 128; j += 2) {
            float v = fmaf(c0v, shW0[j], fmaf(c1v, shW0[128 + j], fmaf(c2v, shW0[256 + j], gw[j])));
            shT[j * HT_STRIDE + r] = fmaxf(v, 0.f);
        }
    }

    const int ty = t >> 4, tx = t & 15;
    const int r0 = ty * 8, c0 = tx * 8;
    float acc[8][8];

    // two residual blocks: h = h + relu(h @ Wb[i] + bb[i])
#pragma unroll 1
    for (int blk = 0; blk < 2; ++blk) {
        __syncthreads();
        const float* Wsrc = Wb + (size_t)blk * 128 * 128;
        for (int i = t * 4; i < 128 * 128; i += 1024)
            *(float4*)(shW + i) = *(const float4*)(Wsrc + i);
        __syncthreads();
        gemm_tile(shT, shW, r0, c0, acc);
        __syncthreads();
        float bv[8];
#pragma unroll
        for (int j = 0; j < 8; ++j) bv[j] = bb[blk * 128 + c0 + j];
#pragma unroll
        for (int i = 0; i < 8; ++i)
#pragma unroll
            for (int j = 0; j < 8; ++j) {
                float v = fmaxf(acc[i][j] + bv[j], 0.f);
                shT[(c0 + j) * HT_STRIDE + (r0 + i)] += v;   // owner-exclusive RMW
            }
    }
    __syncthreads();

    // grad = h @ Wo + bo  (128x3)
    if (t < 128) {
        int r = t;
        float g0 = bo[0], g1 = bo[1], g2 = bo[2];
#pragma unroll 4
        for (int k = 0; k < 128; ++k) {
            float hv = shT[k * HT_STRIDE + r];
            g0 = fmaf(hv, shWo[k * 3 + 0], g0);
            g1 = fmaf(hv, shWo[k * 3 + 1], g1);
            g2 = fmaf(hv, shWo[k * 3 + 2], g2);
        }
        float* gp = g_grad + (((size_t)b * NN + n0) * 4 + r) * 3;
        gp[0] = g0; gp[1] = g1; gp[2] = g2;
    }
}

// ---------------- gather (inverse of clipped scatter) + in-place update ----------------
// acc[m] = sum over (n,k) with clip(n+k-2)==m of grad[n,k]; pcl[m] += s*acc[m]
__global__ void gather_kernel(float* __restrict__ pcl, float s)
{
    int idx = blockIdx.x * blockDim.x + threadIdx.x;
    if (idx >= BN * NN) return;
    int b = idx / NN, m = idx - b * NN;
    const float* G = g_grad + (size_t)b * NN * 12;

    float a0 = 0.f, a1 = 0.f, a2 = 0.f;
#pragma unroll
    for (int k = 0; k < 4; ++k) {
        int n = m + 2 - k;                 // n + (k-2) == m, unclipped
        if (n >= 0 && n < NN) {
            const float* g = G + ((size_t)n * 4 + k) * 3;
            a0 += g[0]; a1 += g[1]; a2 += g[2];
        }
    }
    if (m == 0) {                          // entries clipped up to 0: (0,0),(0,1),(1,0)
        a0 += G[0] + G[3] + G[12];
        a1 += G[1] + G[4] + G[13];
        a2 += G[2] + G[5] + G[14];
    }
    if (m == NN - 1) {                     // entry clipped down to N-1: (N-1,3)
        const float* g = G + (((size_t)(NN - 1)) * 4 + 3) * 3;
        a0 += g[0]; a1 += g[1]; a2 += g[2];
    }
    float* p = pcl + (size_t)idx * 3;
    p[0] += s * a0; p[1] += s * a1; p[2] += s * a2;
}

// ---------------- launch ----------------
extern "C" void kernel_launch(void* const* d_in, const int* in_sizes, int n_in,
                              void* d_out, int out_size)
{
    const float* pcl = (const float*)d_in[0];
    const float* Wf1 = (const float*)d_in[1];
    const float* bf1 = (const float*)d_in[2];
    const float* Wf2 = (const float*)d_in[3];
    const float* bf2 = (const float*)d_in[4];
    const float* W0  = (const float*)d_in[5];
    const float* b0  = (const float*)d_in[6];
    const float* Wb  = (const float*)d_in[7];
    const float* bb  = (const float*)d_in[8];
    const float* Wo  = (const float*)d_in[9];
    const float* bo  = (const float*)d_in[10];
    float* out = (float*)d_out;

    const int SMEM_P = (128 * HT_STRIDE + 128 * 128) * (int)sizeof(float);
    const int SMEM_G = (128 * HT_STRIDE + 128 * 128 + 3 * 128 * 3) * (int)sizeof(float);
    cudaFuncSetAttribute(precompute_kernel, cudaFuncAttributeMaxDynamicSharedMemorySize, SMEM_P);
    cudaFuncSetAttribute(grad_kernel,       cudaFuncAttributeMaxDynamicSharedMemorySize, SMEM_G);

    dim3 gp(NN / 128, BN);
    precompute_kernel<<<gp, 256, SMEM_P>>>(pcl, Wf1, bf1, Wf2, bf2, W0, b0, out);

    float s = 0.2f;
    for (int step = 0; step < 4; ++step) {
        dim3 gg(NN / 32, BN);
        grad_kernel<<<gg, 256, SMEM_G>>>(pcl, out, W0, Wb, bb, Wo, bo);
        gather_kernel<<<(BN * NN + 255) / 256, 256>>>(out, s);
        s *= 0.95f;
    }
}

// round 3
// speedup vs baseline: 3.5482x; 3.5482x over previous
#include <cuda_runtime.h>
#include <cuda_bf16.h>
#include <cstdint>

// ---------------- problem constants ----------------
#define BN 2
#define NN 16384
#define HT_STRIDE 132     // fp32 precompute tile stride
#define BKS 136           // bf16 tile row stride (elements): 272 bytes, conflict-free ldmatrix

// ---------------- device scratch ----------------
__device__ __align__(256) float g_gW0[BN * NN * 128];              // feat @ W0[3:] + b0
__device__ __align__(256) float g_grad[BN * NN * 4 * 3];           // per-(n,k) grad_pred
__device__ __align__(256) __nv_bfloat16 g_Wb[2 * 128 * BKS];       // Wb^T bf16, padded rows

// ================= helpers =================
__device__ __forceinline__ uint32_t smem_u32(const void* p) {
    uint32_t a;
    asm("{ .reg .u64 t; cvta.to.shared.u64 t, %1; cvt.u32.u64 %0, t; }" : "=r"(a) : "l"(p));
    return a;
}
__device__ __forceinline__ void ldsm4(uint32_t r[4], uint32_t addr) {
    asm volatile("ldmatrix.sync.aligned.m8n8.x4.shared.b16 {%0,%1,%2,%3}, [%4];"
                 : "=r"(r[0]), "=r"(r[1]), "=r"(r[2]), "=r"(r[3]) : "r"(addr));
}
__device__ __forceinline__ void mma_bf16(float d[4], const uint32_t a[4],
                                         uint32_t b0, uint32_t b1) {
    asm volatile(
        "mma.sync.aligned.m16n8k16.row.col.f32.bf16.bf16.f32 "
        "{%0,%1,%2,%3}, {%4,%5,%6,%7}, {%8,%9}, {%0,%1,%2,%3};"
        : "+f"(d[0]), "+f"(d[1]), "+f"(d[2]), "+f"(d[3])
        : "r"(a[0]), "r"(a[1]), "r"(a[2]), "r"(a[3]), "r"(b0), "r"(b1));
}

// ================= fp32 microtile GEMM (precompute only) =================
__device__ __forceinline__ void gemm_tile(const float* __restrict__ shT,
                                          const float* __restrict__ shW,
                                          int r0, int c0, float acc[8][8])
{
#pragma unroll
    for (int i = 0; i < 8; ++i)
#pragma unroll
        for (int j = 0; j < 8; ++j) acc[i][j] = 0.f;

#pragma unroll 4
    for (int k = 0; k < 128; ++k) {
        float4 a0 = *(const float4*)(shT + k * HT_STRIDE + r0);
        float4 a1 = *(const float4*)(shT + k * HT_STRIDE + r0 + 4);
        float4 w0 = *(const float4*)(shW + k * 128 + c0);
        float4 w1 = *(const float4*)(shW + k * 128 + c0 + 4);
        float a[8] = {a0.x, a0.y, a0.z, a0.w, a1.x, a1.y, a1.z, a1.w};
        float w[8] = {w0.x, w0.y, w0.z, w0.w, w1.x, w1.y, w1.z, w1.w};
#pragma unroll
        for (int i = 0; i < 8; ++i)
#pragma unroll
            for (int j = 0; j < 8; ++j)
                acc[i][j] = fmaf(a[i], w[j], acc[i][j]);
    }
}

// ================= precompute (fp32, unchanged) =================
__global__ __launch_bounds__(256, 1)
void precompute_kernel(const float* __restrict__ pcl,
                       const float* __restrict__ Wf1, const float* __restrict__ bf1,
                       const float* __restrict__ Wf2, const float* __restrict__ bf2,
                       const float* __restrict__ W0,  const float* __restrict__ b0,
                       float* __restrict__ out)
{
    extern __shared__ float sm[];
    float* shT = sm;
    float* shW = sm + 128 * HT_STRIDE;

    const int t  = threadIdx.x;
    const int b  = blockIdx.y;
    const int n0 = blockIdx.x * 128;
    const float* pclb = pcl + ((size_t)b * NN + n0) * 3;
    float* outb = out + ((size_t)b * NN + n0) * 3;

    for (int i = t; i < 128 * 3; i += 256) outb[i] = pclb[i];

    {
        int r = t & 127;
        int half = t >> 7;
        float x0 = pclb[r * 3 + 0], x1 = pclb[r * 3 + 1], x2 = pclb[r * 3 + 2];
        for (int j = half; j < 128; j += 2) {
            float v = fmaf(x0, Wf1[j], fmaf(x1, Wf1[128 + j], fmaf(x2, Wf1[256 + j], bf1[j])));
            shT[j * HT_STRIDE + r] = fmaxf(v, 0.f);
        }
    }

    const int ty = t >> 4, tx = t & 15;
    const int r0 = ty * 8, c0 = tx * 8;
    float acc[8][8];

    __syncthreads();
    for (int i = t * 4; i < 128 * 128; i += 1024)
        *(float4*)(shW + i) = *(const float4*)(Wf2 + i);
    __syncthreads();
    gemm_tile(shT, shW, r0, c0, acc);
    __syncthreads();
    {
        float bv[8];
#pragma unroll
        for (int j = 0; j < 8; ++j) bv[j] = bf2[c0 + j];
#pragma unroll
        for (int i = 0; i < 8; ++i)
#pragma unroll
            for (int j = 0; j < 8; ++j)
                shT[(c0 + j) * HT_STRIDE + (r0 + i)] = acc[i][j] + bv[j];
    }

    __syncthreads();
    for (int i = t * 4; i < 128 * 128; i += 1024)
        *(float4*)(shW + i) = *(const float4*)(W0 + 3 * 128 + i);
    __syncthreads();
    gemm_tile(shT, shW, r0, c0, acc);
    {
        float bv[8];
#pragma unroll
        for (int j = 0; j < 8; ++j) bv[j] = b0[c0 + j];
        float* gb = g_gW0 + ((size_t)b * NN + n0) * 128;
#pragma unroll
        for (int i = 0; i < 8; ++i) {
            float4 v0 = make_float4(acc[i][0] + bv[0], acc[i][1] + bv[1],
                                    acc[i][2] + bv[2], acc[i][3] + bv[3]);
            float4 v1 = make_float4(acc[i][4] + bv[4], acc[i][5] + bv[5],
                                    acc[i][6] + bv[6], acc[i][7] + bv[7]);
            *(float4*)(gb + (size_t)(r0 + i) * 128 + c0)     = v0;
            *(float4*)(gb + (size_t)(r0 + i) * 128 + c0 + 4) = v1;
        }
    }
}

// ================= Wb -> bf16 transpose/pad (one-shot per launch) =================
__global__ void convert_wb_kernel(const float* __restrict__ Wb)
{
    int idx = blockIdx.x * blockDim.x + threadIdx.x;
    if (idx >= 2 * 128 * 128) return;
    int blk = idx >> 14;
    int rem = idx & 16383;
    int n = rem >> 7, k = rem & 127;
    g_Wb[blk * 128 * BKS + n * BKS + k] = __float2bfloat16(Wb[blk * 16384 + k * 128 + n]);
}

// ================= grad kernel: mma.sync bf16 =================
// 256 threads (8 warps), 128 rows (32 points x 4 nbrs).
// SMEM: A_s [128][BKS] bf16 (34816B) | B_s 2x[128][BKS] bf16 (69632B) | W0/Wo/bb fp32
#define A_BYTES   (128 * BKS * 2)
#define B_BYTES   (2 * 128 * BKS * 2)
#define GK_SMEM   (A_BYTES + B_BYTES + (384 + 384 + 256) * 4)

__global__ __launch_bounds__(256, 1)
void grad_kernel_mma(const float* __restrict__ pcl_noisy, const float* __restrict__ pcl_cur,
                     const float* __restrict__ W0, const float* __restrict__ bb,
                     const float* __restrict__ Wo, const float* __restrict__ bo)
{
    extern __shared__ __align__(256) char smc[];
    const int t    = threadIdx.x;
    const int lane = t & 31;
    const int w    = t >> 5;
    const int b    = blockIdx.y;
    const int n0   = blockIdx.x * 32;

    char* A_s = smc;
    char* B_s = smc + A_BYTES;
    float* shW0 = (float*)(smc + A_BYTES + B_BYTES);
    float* shWo = shW0 + 384;
    float* shBB = shWo + 384;

    const uint32_t Abase = smem_u32(A_s);
    const uint32_t Bbase = smem_u32(B_s);

    // stage weights / small arrays
    for (int i = t; i < 384; i += 256) { shW0[i] = W0[i]; shWo[i] = Wo[i]; }
    for (int i = t; i < 256; i += 256 /*once*/) {}
    for (int i = t; i < 256; i += 256) shBB[i] = bb[i];
    {
        const uint4* src = (const uint4*)g_Wb;
        uint4* dst = (uint4*)B_s;
        for (int i = t; i < B_BYTES / 16; i += 256) dst[i] = src[i];
    }

    // h0 = relu(centered @ W0[:3] + gW0) -> A_s (bf16)
    {
        int r = t & 127, half = t >> 7;
        int p = r >> 2, q = r & 3;
        int n = n0 + p;
        int m = n + q - 2;
        m = m < 0 ? 0 : (m > NN - 1 ? NN - 1 : m);
        const float* pc = pcl_cur   + ((size_t)b * NN + m) * 3;
        const float* pn = pcl_noisy + ((size_t)b * NN + n) * 3;
        float c0 = pc[0] - pn[0], c1 = pc[1] - pn[1], c2 = pc[2] - pn[2];
        const float* gw = g_gW0 + ((size_t)b * NN + n) * 128;
        __syncthreads();   // shW0 ready
#pragma unroll 4
        for (int j = half * 64; j < half * 64 + 64; j += 2) {
            float v0 = fmaf(c0, shW0[j],     fmaf(c1, shW0[128 + j],     fmaf(c2, shW0[256 + j],     gw[j])));
            float v1 = fmaf(c0, shW0[j + 1], fmaf(c1, shW0[128 + j + 1], fmaf(c2, shW0[256 + j + 1], gw[j + 1])));
            *(__nv_bfloat162*)(A_s + r * (BKS * 2) + j * 2) =
                __floats2bfloat162_rn(fmaxf(v0, 0.f), fmaxf(v1, 0.f));
        }
    }
    __syncthreads();

    // fragment geometry
    const int mrow = w * 16;
    const int rgrp = lane >> 2;            // 0..7
    const int cpos = (lane & 3) * 2;       // 0,2,4,6

    // per-thread ldmatrix base addresses
    const uint32_t aAddrBase = Abase
        + (uint32_t)((mrow + (lane & 7) + (((lane >> 3) & 1) << 3)) * (BKS * 2))
        + (uint32_t)(((lane >> 4) << 3) * 2);
    const uint32_t bAddrBase0 = Bbase
        + (uint32_t)(((lane & 7) + ((lane >> 4) << 3)) * (BKS * 2))
        + (uint32_t)(((lane >> 3) & 1) << 4);

    // load fp32 h fragment copy from A_s
    float h[16][4];
#pragma unroll
    for (int j = 0; j < 16; ++j) {
        int c = j * 8 + cpos;
        float2 p0 = __bfloat1622float2(*(__nv_bfloat162*)(A_s + (mrow + rgrp) * (BKS * 2) + c * 2));
        float2 p1 = __bfloat1622float2(*(__nv_bfloat162*)(A_s + (mrow + rgrp + 8) * (BKS * 2) + c * 2));
        h[j][0] = p0.x; h[j][1] = p0.y; h[j][2] = p1.x; h[j][3] = p1.y;
    }

#pragma unroll 1
    for (int blk = 0; blk < 2; ++blk) {
        float acc[16][4];
#pragma unroll
        for (int j = 0; j < 16; ++j)
#pragma unroll
            for (int i = 0; i < 4; ++i) acc[j][i] = 0.f;

        const uint32_t bblk = bAddrBase0 + (uint32_t)blk * (128 * BKS * 2);

#pragma unroll
        for (int s = 0; s < 8; ++s) {
            uint32_t a[4];
            ldsm4(a, aAddrBase + s * 32);
#pragma unroll
            for (int jp = 0; jp < 8; ++jp) {
                uint32_t bf[4];
                ldsm4(bf, bblk + (uint32_t)(jp * 16 * (BKS * 2)) + s * 32);
                mma_bf16(acc[2 * jp],     a, bf[0], bf[1]);
                mma_bf16(acc[2 * jp + 1], a, bf[2], bf[3]);
            }
        }

        __syncthreads();   // all ldmatrix reads of A_s done before rewriting it

        // epilogue: h += relu(acc + bb); write bf16 h back to A_s
#pragma unroll
        for (int j = 0; j < 16; ++j) {
            int c = j * 8 + cpos;
            float b0v = shBB[blk * 128 + c], b1v = shBB[blk * 128 + c + 1];
            h[j][0] += fmaxf(acc[j][0] + b0v, 0.f);
            h[j][1] += fmaxf(acc[j][1] + b1v, 0.f);
            h[j][2] += fmaxf(acc[j][2] + b0v, 0.f);
            h[j][3] += fmaxf(acc[j][3] + b1v, 0.f);
            *(__nv_bfloat162*)(A_s + (mrow + rgrp) * (BKS * 2) + c * 2) =
                __floats2bfloat162_rn(h[j][0], h[j][1]);
            *(__nv_bfloat162*)(A_s + (mrow + rgrp + 8) * (BKS * 2) + c * 2) =
                __floats2bfloat162_rn(h[j][2], h[j][3]);
        }
        __syncthreads();
    }

    // grad = h @ Wo + bo (fp32 h in regs), reduce across 4 lanes per row
    {
        float g0[3] = {0.f, 0.f, 0.f}, g1[3] = {0.f, 0.f, 0.f};
#pragma unroll
        for (int j = 0; j < 16; ++j) {
            int c = j * 8 + cpos;
#pragma unroll
            for (int d = 0; d < 3; ++d) {
                float w0v = shWo[c * 3 + d], w1v = shWo[(c + 1) * 3 + d];
                g0[d] = fmaf(h[j][0], w0v, fmaf(h[j][1], w1v, g0[d]));
                g1[d] = fmaf(h[j][2], w0v, fmaf(h[j][3], w1v, g1[d]));
            }
        }
#pragma unroll
        for (int d = 0; d < 3; ++d) {
            g0[d] += __shfl_xor_sync(0xffffffffu, g0[d], 1);
            g0[d] += __shfl_xor_sync(0xffffffffu, g0[d], 2);
            g1[d] += __shfl_xor_sync(0xffffffffu, g1[d], 1);
            g1[d] += __shfl_xor_sync(0xffffffffu, g1[d], 2);
        }
        if ((lane & 3) == 0) {
            int r = mrow + rgrp;
            float* gp0 = g_grad + (((size_t)b * NN + n0) * 4 + r) * 3;
            float* gp1 = g_grad + (((size_t)b * NN + n0) * 4 + r + 8) * 3;
            gp0[0] = g0[0] + bo[0]; gp0[1] = g0[1] + bo[1]; gp0[2] = g0[2] + bo[2];
            gp1[0] = g1[0] + bo[0]; gp1[1] = g1[1] + bo[1]; gp1[2] = g1[2] + bo[2];
        }
    }
}

// ================= gather + update =================
__global__ void gather_kernel(float* __restrict__ pcl, float s)
{
    int idx = blockIdx.x * blockDim.x + threadIdx.x;
    if (idx >= BN * NN) return;
    int b = idx / NN, m = idx - b * NN;
    const float* G = g_grad + (size_t)b * NN * 12;

    float a0 = 0.f, a1 = 0.f, a2 = 0.f;
#pragma unroll
    for (int k = 0; k < 4; ++k) {
        int n = m + 2 - k;
        if (n >= 0 && n < NN) {
            const float* g = G + ((size_t)n * 4 + k) * 3;
            a0 += g[0]; a1 += g[1]; a2 += g[2];
        }
    }
    if (m == 0) {
        a0 += G[0] + G[3] + G[12];
        a1 += G[1] + G[4] + G[13];
        a2 += G[2] + G[5] + G[14];
    }
    if (m == NN - 1) {
        const float* g = G + (((size_t)(NN - 1)) * 4 + 3) * 3;
        a0 += g[0]; a1 += g[1]; a2 += g[2];
    }
    float* p = pcl + (size_t)idx * 3;
    p[0] += s * a0; p[1] += s * a1; p[2] += s * a2;
}

// ================= launch =================
extern "C" void kernel_launch(void* const* d_in, const int* in_sizes, int n_in,
                              void* d_out, int out_size)
{
    const float* pcl = (const float*)d_in[0];
    const float* Wf1 = (const float*)d_in[1];
    const float* bf1 = (const float*)d_in[2];
    const float* Wf2 = (const float*)d_in[3];
    const float* bf2 = (const float*)d_in[4];
    const float* W0  = (const float*)d_in[5];
    const float* b0  = (const float*)d_in[6];
    const float* Wb  = (const float*)d_in[7];
    const float* bb  = (const float*)d_in[8];
    const float* Wo  = (const float*)d_in[9];
    const float* bo  = (const float*)d_in[10];
    float* out = (float*)d_out;

    const int SMEM_P = (128 * HT_STRIDE + 128 * 128) * (int)sizeof(float);
    cudaFuncSetAttribute(precompute_kernel, cudaFuncAttributeMaxDynamicSharedMemorySize, SMEM_P);
    cudaFuncSetAttribute(grad_kernel_mma,   cudaFuncAttributeMaxDynamicSharedMemorySize, GK_SMEM);

    convert_wb_kernel<<<(2 * 128 * 128 + 255) / 256, 256>>>(Wb);

    dim3 gp(NN / 128, BN);
    precompute_kernel<<<gp, 256, SMEM_P>>>(pcl, Wf1, bf1, Wf2, bf2, W0, b0, out);

    float s = 0.2f;
    for (int step = 0; step < 4; ++step) {
        dim3 gg(NN / 32, BN);
        grad_kernel_mma<<<gg, 256, GK_SMEM>>>(pcl, out, W0, bb, Wo, bo);
        gather_kernel<<<(BN * NN + 255) / 256, 256>>>(out, s);
        s *= 0.95f;
    }
}

// round 4
// speedup vs baseline: 5.0568x; 1.4252x over previous
#include <cuda_runtime.h>
#include <cuda_bf16.h>
#include <cstdint>

// ---------------- problem constants ----------------
#define BN 2
#define NN 16384
#define BKS 136           // bf16 tile row stride (elements): 272 bytes, conflict-free ldmatrix
#define GRID_P 148        // persistent grid
#define N_TILES_G (BN * NN / 32)    // 1024 grad tiles (32 points x 4 nbrs = 128 rows)
#define N_TILES_P (BN * NN / 128)   // 256 precompute tiles (128 rows)

// ---------------- device scratch ----------------
__device__ __align__(256) float g_gW0[BN * NN * 128];              // feat @ W0[3:] + b0
__device__ __align__(256) float g_grad[BN * NN * 4 * 3];           // per-(n,k) grad_pred
__device__ __align__(256) __nv_bfloat16 g_Wb[2 * 128 * BKS];       // Wb^T bf16, padded
__device__ __align__(256) __nv_bfloat16 g_Wf2T[128 * BKS];         // Wf2^T bf16
__device__ __align__(256) __nv_bfloat16 g_W03T[128 * BKS];         // (W0[3:])^T bf16

// ================= helpers =================
__device__ __forceinline__ uint32_t smem_u32(const void* p) {
    uint32_t a;
    asm("{ .reg .u64 t; cvta.to.shared.u64 t, %1; cvt.u32.u64 %0, t; }" : "=r"(a) : "l"(p));
    return a;
}
__device__ __forceinline__ void ldsm4(uint32_t r[4], uint32_t addr) {
    asm volatile("ldmatrix.sync.aligned.m8n8.x4.shared.b16 {%0,%1,%2,%3}, [%4];"
                 : "=r"(r[0]), "=r"(r[1]), "=r"(r[2]), "=r"(r[3]) : "r"(addr));
}
__device__ __forceinline__ void mma_bf16(float d[4], const uint32_t a[4],
                                         uint32_t b0, uint32_t b1) {
    asm volatile(
        "mma.sync.aligned.m16n8k16.row.col.f32.bf16.bf16.f32 "
        "{%0,%1,%2,%3}, {%4,%5,%6,%7}, {%8,%9}, {%0,%1,%2,%3};"
        : "+f"(d[0]), "+f"(d[1]), "+f"(d[2]), "+f"(d[3])
        : "r"(a[0]), "r"(a[1]), "r"(a[2]), "r"(a[3]), "r"(b0), "r"(b1));
}

// warp-level 128x128x128 GEMM: A frags from aAddr (16 rows/warp slice), full 128-col B
__device__ __forceinline__ void warp_gemm(uint32_t aAddr, uint32_t bAddr, float acc[16][4]) {
#pragma unroll
    for (int j = 0; j < 16; ++j)
#pragma unroll
        for (int i = 0; i < 4; ++i) acc[j][i] = 0.f;
#pragma unroll
    for (int s = 0; s < 8; ++s) {
        uint32_t a[4];
        ldsm4(a, aAddr + s * 32);
#pragma unroll
        for (int jp = 0; jp < 8; ++jp) {
            uint32_t bf[4];
            ldsm4(bf, bAddr + (uint32_t)(jp * 16 * (BKS * 2)) + s * 32);
            mma_bf16(acc[2 * jp],     a, bf[0], bf[1]);
            mma_bf16(acc[2 * jp + 1], a, bf[2], bf[3]);
        }
    }
}

// ================= convert: all weights -> bf16 transposed/padded =================
__global__ void convert_w_kernel(const float* __restrict__ Wb,
                                 const float* __restrict__ Wf2,
                                 const float* __restrict__ W0)
{
    int idx = blockIdx.x * blockDim.x + threadIdx.x;
    if (idx >= 4 * 128 * 128) return;
    int seg = idx >> 14;
    int rem = idx & 16383;
    int n = rem >> 7, k = rem & 127;
    if (seg < 2) {
        g_Wb[seg * 128 * BKS + n * BKS + k] = __float2bfloat16(Wb[seg * 16384 + k * 128 + n]);
    } else if (seg == 2) {
        g_Wf2T[n * BKS + k] = __float2bfloat16(Wf2[k * 128 + n]);
    } else {
        g_W03T[n * BKS + k] = __float2bfloat16(W0[(3 + k) * 128 + n]);
    }
}

// ================= shared SMEM layout =================
#define A_BYTES   (128 * BKS * 2)           // 34816
#define B_BYTES   (2 * 128 * BKS * 2)       // 69632
#define MISC_BYTES 4096
#define GK_SMEM   (A_BYTES + B_BYTES + MISC_BYTES)

// ================= precompute via mma (persistent) =================
// misc: Wf1 384 | bf1 128 | bf2 128 | b0 128 floats
__global__ __launch_bounds__(256, 1)
void precompute_mma(const float* __restrict__ pcl,
                    const float* __restrict__ Wf1, const float* __restrict__ bf1,
                    const float* __restrict__ bf2, const float* __restrict__ b0,
                    float* __restrict__ out)
{
    extern __shared__ __align__(256) char smc[];
    const int t    = threadIdx.x;
    const int lane = t & 31;
    const int w    = t >> 5;

    char* A_s = smc;
    char* B_s = smc + A_BYTES;
    float* shWf1 = (float*)(smc + A_BYTES + B_BYTES);
    float* shbf1 = shWf1 + 384;
    float* shbf2 = shbf1 + 128;
    float* shb0  = shbf2 + 128;

    // stage weights once
    for (int i = t; i < 384; i += 256) shWf1[i] = Wf1[i];
    if (t < 128) { shbf1[t] = bf1[t]; shbf2[t] = bf2[t]; shb0[t] = b0[t]; }
    {
        const uint4* s1 = (const uint4*)g_Wf2T;
        const uint4* s2 = (const uint4*)g_W03T;
        uint4* d1 = (uint4*)B_s;
        uint4* d2 = (uint4*)(B_s + A_BYTES);
        for (int i = t; i < A_BYTES / 16; i += 256) { d1[i] = s1[i]; d2[i] = s2[i]; }
    }
    __syncthreads();

    const uint32_t Abase = smem_u32(A_s);
    const uint32_t Bbase = smem_u32(B_s);
    const int mrow = w * 16;
    const int rgrp = lane >> 2;
    const int cpos = (lane & 3) * 2;
    const uint32_t aAddr = Abase
        + (uint32_t)((mrow + (lane & 7) + (((lane >> 3) & 1) << 3)) * (BKS * 2))
        + (uint32_t)(((lane >> 4) << 3) * 2);
    const uint32_t bAddr = Bbase
        + (uint32_t)(((lane & 7) + ((lane >> 4) << 3)) * (BKS * 2))
        + (uint32_t)(((lane >> 3) & 1) << 4);

    for (int tile = blockIdx.x; tile < N_TILES_P; tile += GRID_P) {
        int b  = tile / (NN / 128);
        int n0 = (tile % (NN / 128)) * 128;
        const float* pclb = pcl + ((size_t)b * NN + n0) * 3;
        float* outb = out + ((size_t)b * NN + n0) * 3;

        // out = pcl copy
        for (int i = t; i < 128 * 3; i += 256) outb[i] = pclb[i];

        // h1 = relu(pcl @ Wf1 + bf1) -> A_s bf16
        {
            int r = t & 127, half = t >> 7;
            float x0 = pclb[r * 3 + 0], x1 = pclb[r * 3 + 1], x2 = pclb[r * 3 + 2];
#pragma unroll 4
            for (int j = half * 64; j < half * 64 + 64; j += 2) {
                float v0 = fmaf(x0, shWf1[j],     fmaf(x1, shWf1[128 + j],     fmaf(x2, shWf1[256 + j],     shbf1[j])));
                float v1 = fmaf(x0, shWf1[j + 1], fmaf(x1, shWf1[128 + j + 1], fmaf(x2, shWf1[256 + j + 1], shbf1[j + 1])));
                *(__nv_bfloat162*)(A_s + r * (BKS * 2) + j * 2) =
                    __floats2bfloat162_rn(fmaxf(v0, 0.f), fmaxf(v1, 0.f));
            }
        }
        __syncthreads();

        float acc[16][4];

        // GEMM1: feat = h1 @ Wf2 + bf2 (no relu) -> A_s bf16
        warp_gemm(aAddr, bAddr, acc);
        __syncthreads();
#pragma unroll
        for (int j = 0; j < 16; ++j) {
            int c = j * 8 + cpos;
            float b0v = shbf2[c], b1v = shbf2[c + 1];
            *(__nv_bfloat162*)(A_s + (mrow + rgrp) * (BKS * 2) + c * 2) =
                __floats2bfloat162_rn(acc[j][0] + b0v, acc[j][1] + b1v);
            *(__nv_bfloat162*)(A_s + (mrow + rgrp + 8) * (BKS * 2) + c * 2) =
                __floats2bfloat162_rn(acc[j][2] + b0v, acc[j][3] + b1v);
        }
        __syncthreads();

        // GEMM2: gW0 = feat @ W0[3:] + b0 -> global fp32
        warp_gemm(aAddr, bAddr + (uint32_t)A_BYTES, acc);
        {
            float* gb = g_gW0 + ((size_t)b * NN + n0) * 128;
#pragma unroll
            for (int j = 0; j < 16; ++j) {
                int c = j * 8 + cpos;
                float b0v = shb0[c], b1v = shb0[c + 1];
                *(float2*)(gb + (size_t)(mrow + rgrp) * 128 + c) =
                    make_float2(acc[j][0] + b0v, acc[j][1] + b1v);
                *(float2*)(gb + (size_t)(mrow + rgrp + 8) * 128 + c) =
                    make_float2(acc[j][2] + b0v, acc[j][3] + b1v);
            }
        }
        __syncthreads();   // gb writes done before next tile rewrites A_s (A_s reads done too)
    }
}

// ================= grad kernel: persistent mma.sync bf16 =================
// misc: W0 384 | Wo 384 | bb 256 floats
__global__ __launch_bounds__(256, 1)
void grad_kernel_mma(const float* __restrict__ pcl_noisy, const float* __restrict__ pcl_cur,
                     const float* __restrict__ W0, const float* __restrict__ bb,
                     const float* __restrict__ Wo, const float* __restrict__ bo)
{
    extern __shared__ __align__(256) char smc[];
    const int t    = threadIdx.x;
    const int lane = t & 31;
    const int w    = t >> 5;

    char* A_s = smc;
    char* B_s = smc + A_BYTES;
    float* shW0 = (float*)(smc + A_BYTES + B_BYTES);
    float* shWo = shW0 + 384;
    float* shBB = shWo + 384;

    for (int i = t; i < 384; i += 256) { shW0[i] = W0[i]; shWo[i] = Wo[i]; }
    if (t < 256) shBB[t] = bb[t];
    {
        const uint4* src = (const uint4*)g_Wb;
        uint4* dst = (uint4*)B_s;
        for (int i = t; i < B_BYTES / 16; i += 256) dst[i] = src[i];
    }
    __syncthreads();

    const uint32_t Abase = smem_u32(A_s);
    const uint32_t Bbase = smem_u32(B_s);
    const int mrow = w * 16;
    const int rgrp = lane >> 2;
    const int cpos = (lane & 3) * 2;
    const uint32_t aAddr = Abase
        + (uint32_t)((mrow + (lane & 7) + (((lane >> 3) & 1) << 3)) * (BKS * 2))
        + (uint32_t)(((lane >> 4) << 3) * 2);
    const uint32_t bAddr = Bbase
        + (uint32_t)(((lane & 7) + ((lane >> 4) << 3)) * (BKS * 2))
        + (uint32_t)(((lane >> 3) & 1) << 4);

    const float bo0 = bo[0], bo1 = bo[1], bo2 = bo[2];

    for (int tile = blockIdx.x; tile < N_TILES_G; tile += GRID_P) {
        int b  = tile >> 9;                  // NN/32 = 512 tiles per batch
        int n0 = (tile & 511) * 32;

        // h0 = relu(centered @ W0[:3] + gW0) -> A_s bf16
        {
            int r = t & 127, half = t >> 7;
            int p = r >> 2, q = r & 3;
            int n = n0 + p;
            int m = n + q - 2;
            m = m < 0 ? 0 : (m > NN - 1 ? NN - 1 : m);
            const float* pc = pcl_cur   + ((size_t)b * NN + m) * 3;
            const float* pn = pcl_noisy + ((size_t)b * NN + n) * 3;
            float c0 = pc[0] - pn[0], c1 = pc[1] - pn[1], c2 = pc[2] - pn[2];
            const float* gw = g_gW0 + ((size_t)b * NN + n) * 128;
#pragma unroll 4
            for (int j = half * 64; j < half * 64 + 64; j += 2) {
                float v0 = fmaf(c0, shW0[j],     fmaf(c1, shW0[128 + j],     fmaf(c2, shW0[256 + j],     gw[j])));
                float v1 = fmaf(c0, shW0[j + 1], fmaf(c1, shW0[128 + j + 1], fmaf(c2, shW0[256 + j + 1], gw[j + 1])));
                *(__nv_bfloat162*)(A_s + r * (BKS * 2) + j * 2) =
                    __floats2bfloat162_rn(fmaxf(v0, 0.f), fmaxf(v1, 0.f));
            }
        }
        __syncthreads();

        // fp32 h fragment copy
        float h[16][4];
#pragma unroll
        for (int j = 0; j < 16; ++j) {
            int c = j * 8 + cpos;
            float2 p0 = __bfloat1622float2(*(__nv_bfloat162*)(A_s + (mrow + rgrp) * (BKS * 2) + c * 2));
            float2 p1 = __bfloat1622float2(*(__nv_bfloat162*)(A_s + (mrow + rgrp + 8) * (BKS * 2) + c * 2));
            h[j][0] = p0.x; h[j][1] = p0.y; h[j][2] = p1.x; h[j][3] = p1.y;
        }

        float acc[16][4];

        // residual block 0: h += relu(h@Wb0 + bb0); writeback bf16 h to A_s
        warp_gemm(aAddr, bAddr, acc);
        __syncthreads();
#pragma unroll
        for (int j = 0; j < 16; ++j) {
            int c = j * 8 + cpos;
            float b0v = shBB[c], b1v = shBB[c + 1];
            h[j][0] += fmaxf(acc[j][0] + b0v, 0.f);
            h[j][1] += fmaxf(acc[j][1] + b1v, 0.f);
            h[j][2] += fmaxf(acc[j][2] + b0v, 0.f);
            h[j][3] += fmaxf(acc[j][3] + b1v, 0.f);
            *(__nv_bfloat162*)(A_s + (mrow + rgrp) * (BKS * 2) + c * 2) =
                __floats2bfloat162_rn(h[j][0], h[j][1]);
            *(__nv_bfloat162*)(A_s + (mrow + rgrp + 8) * (BKS * 2) + c * 2) =
                __floats2bfloat162_rn(h[j][2], h[j][3]);
        }
        __syncthreads();

        // residual block 1: regs only (no A_s writeback needed)
        warp_gemm(aAddr, bAddr + (uint32_t)(128 * BKS * 2), acc);
        __syncthreads();   // all A_s ldsm reads complete before next tile rewrites
#pragma unroll
        for (int j = 0; j < 16; ++j) {
            int c = j * 8 + cpos;
            float b0v = shBB[128 + c], b1v = shBB[128 + c + 1];
            h[j][0] += fmaxf(acc[j][0] + b0v, 0.f);
            h[j][1] += fmaxf(acc[j][1] + b1v, 0.f);
            h[j][2] += fmaxf(acc[j][2] + b0v, 0.f);
            h[j][3] += fmaxf(acc[j][3] + b1v, 0.f);
        }

        // grad = h @ Wo + bo, reduce over 4 lanes
        {
            float g0[3] = {0.f, 0.f, 0.f}, g1[3] = {0.f, 0.f, 0.f};
#pragma unroll
            for (int j = 0; j < 16; ++j) {
                int c = j * 8 + cpos;
#pragma unroll
                for (int d = 0; d < 3; ++d) {
                    float w0v = shWo[c * 3 + d], w1v = shWo[(c + 1) * 3 + d];
                    g0[d] = fmaf(h[j][0], w0v, fmaf(h[j][1], w1v, g0[d]));
                    g1[d] = fmaf(h[j][2], w0v, fmaf(h[j][3], w1v, g1[d]));
                }
            }
#pragma unroll
            for (int d = 0; d < 3; ++d) {
                g0[d] += __shfl_xor_sync(0xffffffffu, g0[d], 1);
                g0[d] += __shfl_xor_sync(0xffffffffu, g0[d], 2);
                g1[d] += __shfl_xor_sync(0xffffffffu, g1[d], 1);
                g1[d] += __shfl_xor_sync(0xffffffffu, g1[d], 2);
            }
            if ((lane & 3) == 0) {
                int r = mrow + rgrp;
                float* gp0 = g_grad + (((size_t)b * NN + n0) * 4 + r) * 3;
                float* gp1 = g_grad + (((size_t)b * NN + n0) * 4 + r + 8) * 3;
                gp0[0] = g0[0] + bo0; gp0[1] = g0[1] + bo1; gp0[2] = g0[2] + bo2;
                gp1[0] = g1[0] + bo0; gp1[1] = g1[1] + bo1; gp1[2] = g1[2] + bo2;
            }
        }
    }
}

// ================= gather + update =================
__global__ void gather_kernel(float* __restrict__ pcl, float s)
{
    int idx = blockIdx.x * blockDim.x + threadIdx.x;
    if (idx >= BN * NN) return;
    int b = idx / NN, m = idx - b * NN;
    const float* G = g_grad + (size_t)b * NN * 12;

    float a0 = 0.f, a1 = 0.f, a2 = 0.f;
#pragma unroll
    for (int k = 0; k < 4; ++k) {
        int n = m + 2 - k;
        if (n >= 0 && n < NN) {
            const float* g = G + ((size_t)n * 4 + k) * 3;
            a0 += g[0]; a1 += g[1]; a2 += g[2];
        }
    }
    if (m == 0) {
        a0 += G[0] + G[3] + G[12];
        a1 += G[1] + G[4] + G[13];
        a2 += G[2] + G[5] + G[14];
    }
    if (m == NN - 1) {
        const float* g = G + (((size_t)(NN - 1)) * 4 + 3) * 3;
        a0 += g[0]; a1 += g[1]; a2 += g[2];
    }
    float* p = pcl + (size_t)idx * 3;
    p[0] += s * a0; p[1] += s * a1; p[2] += s * a2;
}

// ================= launch =================
extern "C" void kernel_launch(void* const* d_in, const int* in_sizes, int n_in,
                              void* d_out, int out_size)
{
    const float* pcl = (const float*)d_in[0];
    const float* Wf1 = (const float*)d_in[1];
    const float* bf1 = (const float*)d_in[2];
    const float* Wf2 = (const float*)d_in[3];
    const float* bf2 = (const float*)d_in[4];
    const float* W0  = (const float*)d_in[5];
    const float* b0  = (const float*)d_in[6];
    const float* Wb  = (const float*)d_in[7];
    const float* bb  = (const float*)d_in[8];
    const float* Wo  = (const float*)d_in[9];
    const float* bo  = (const float*)d_in[10];
    float* out = (float*)d_out;

    cudaFuncSetAttribute(precompute_mma, cudaFuncAttributeMaxDynamicSharedMemorySize, GK_SMEM);
    cudaFuncSetAttribute(grad_kernel_mma, cudaFuncAttributeMaxDynamicSharedMemorySize, GK_SMEM);

    convert_w_kernel<<<(4 * 128 * 128 + 255) / 256, 256>>>(Wb, Wf2, W0);
    precompute_mma<<<GRID_P, 256, GK_SMEM>>>(pcl, Wf1, bf1, bf2, b0, out);

    float s = 0.2f;
    for (int step = 0; step < 4; ++step) {
        grad_kernel_mma<<<GRID_P, 256, GK_SMEM>>>(pcl, out, W0, bb, Wo, bo);
        gather_kernel<<<(BN * NN + 255) / 256, 256>>>(out, s);
        s *= 0.95f;
    }
}

// round 5
// speedup vs baseline: 5.9920x; 1.1849x over previous
#include <cuda_runtime.h>
#include <cuda_bf16.h>
#include <cstdint>

// ---------------- problem constants ----------------
#define BN 2
#define NN 16384
#define BKS 136           // bf16 tile row stride (elements): 272 bytes, conflict-free ldmatrix
#define GRID_P 296        // persistent grid: 148 SMs x 2 CTAs
#define N_TILES_G (BN * NN / 32)    // 1024 grad tiles (32 points x 4 nbrs = 128 rows)
#define N_TILES_P (BN * NN / 128)   // 256 precompute tiles (128 rows)

// ---------------- device scratch ----------------
__device__ __align__(256) float g_gW0[BN * NN * 128];              // feat @ W0[3:] + b0
__device__ __align__(256) float g_grad[BN * NN * 4 * 3];           // per-(n,k) grad_pred
__device__ __align__(256) __nv_bfloat16 g_Wb[2 * 128 * BKS];       // Wb^T bf16, padded
__device__ __align__(256) __nv_bfloat16 g_Wf2T[128 * BKS];         // Wf2^T bf16
__device__ __align__(256) __nv_bfloat16 g_W03T[128 * BKS];         // (W0[3:])^T bf16

// ================= helpers =================
__device__ __forceinline__ uint32_t smem_u32(const void* p) {
    uint32_t a;
    asm("{ .reg .u64 t; cvta.to.shared.u64 t, %1; cvt.u32.u64 %0, t; }" : "=r"(a) : "l"(p));
    return a;
}
__device__ __forceinline__ void ldsm4(uint32_t r[4], uint32_t addr) {
    asm volatile("ldmatrix.sync.aligned.m8n8.x4.shared.b16 {%0,%1,%2,%3}, [%4];"
                 : "=r"(r[0]), "=r"(r[1]), "=r"(r[2]), "=r"(r[3]) : "r"(addr));
}
__device__ __forceinline__ void mma_bf16(float d[4], const uint32_t a[4],
                                         uint32_t b0, uint32_t b1) {
    asm volatile(
        "mma.sync.aligned.m16n8k16.row.col.f32.bf16.bf16.f32 "
        "{%0,%1,%2,%3}, {%4,%5,%6,%7}, {%8,%9}, {%0,%1,%2,%3};"
        : "+f"(d[0]), "+f"(d[1]), "+f"(d[2]), "+f"(d[3])
        : "r"(a[0]), "r"(a[1]), "r"(a[2]), "r"(a[3]), "r"(b0), "r"(b1));
}

// warp-level 128x128x128 GEMM: A frags from aAddr (16 rows/warp slice), full 128-col B
__device__ __forceinline__ void warp_gemm(uint32_t aAddr, uint32_t bAddr, float acc[16][4]) {
#pragma unroll
    for (int j = 0; j < 16; ++j)
#pragma unroll
        for (int i = 0; i < 4; ++i) acc[j][i] = 0.f;
#pragma unroll
    for (int s = 0; s < 8; ++s) {
        uint32_t a[4];
        ldsm4(a, aAddr + s * 32);
#pragma unroll
        for (int jp = 0; jp < 8; ++jp) {
            uint32_t bf[4];
            ldsm4(bf, bAddr + (uint32_t)(jp * 16 * (BKS * 2)) + s * 32);
            mma_bf16(acc[2 * jp],     a, bf[0], bf[1]);
            mma_bf16(acc[2 * jp + 1], a, bf[2], bf[3]);
        }
    }
}

// ================= convert: all weights -> bf16 transposed/padded =================
__global__ void convert_w_kernel(const float* __restrict__ Wb,
                                 const float* __restrict__ Wf2,
                                 const float* __restrict__ W0)
{
    int idx = blockIdx.x * blockDim.x + threadIdx.x;
    if (idx >= 4 * 128 * 128) return;
    int seg = idx >> 14;
    int rem = idx & 16383;
    int n = rem >> 7, k = rem & 127;
    if (seg < 2) {
        g_Wb[seg * 128 * BKS + n * BKS + k] = __float2bfloat16(Wb[seg * 16384 + k * 128 + n]);
    } else if (seg == 2) {
        g_Wf2T[n * BKS + k] = __float2bfloat16(Wf2[k * 128 + n]);
    } else {
        g_W03T[n * BKS + k] = __float2bfloat16(W0[(3 + k) * 128 + n]);
    }
}

// ================= shared SMEM layout =================
#define A_BYTES   (128 * BKS * 2)           // 34816
#define B_BYTES   (2 * 128 * BKS * 2)       // 69632
#define MISC_BYTES 4096
#define GK_SMEM   (A_BYTES + B_BYTES + MISC_BYTES)   // 108544 -> 2 CTAs/SM

// ================= precompute via mma (persistent) =================
__global__ __launch_bounds__(256, 2)
void precompute_mma(const float* __restrict__ pcl,
                    const float* __restrict__ Wf1, const float* __restrict__ bf1,
                    const float* __restrict__ bf2, const float* __restrict__ b0,
                    float* __restrict__ out)
{
    extern __shared__ __align__(256) char smc[];
    const int t    = threadIdx.x;
    const int lane = t & 31;
    const int w    = t >> 5;

    char* A_s = smc;
    char* B_s = smc + A_BYTES;
    float* shWf1 = (float*)(smc + A_BYTES + B_BYTES);
    float* shbf1 = shWf1 + 384;
    float* shbf2 = shbf1 + 128;
    float* shb0  = shbf2 + 128;

    for (int i = t; i < 384; i += 256) shWf1[i] = Wf1[i];
    if (t < 128) { shbf1[t] = bf1[t]; shbf2[t] = bf2[t]; shb0[t] = b0[t]; }
    {
        const uint4* s1 = (const uint4*)g_Wf2T;
        const uint4* s2 = (const uint4*)g_W03T;
        uint4* d1 = (uint4*)B_s;
        uint4* d2 = (uint4*)(B_s + A_BYTES);
        for (int i = t; i < A_BYTES / 16; i += 256) { d1[i] = s1[i]; d2[i] = s2[i]; }
    }
    __syncthreads();

    const uint32_t Abase = smem_u32(A_s);
    const uint32_t Bbase = smem_u32(B_s);
    const int mrow = w * 16;
    const int rgrp = lane >> 2;
    const int cpos = (lane & 3) * 2;
    const uint32_t aAddr = Abase
        + (uint32_t)((mrow + (lane & 7) + (((lane >> 3) & 1) << 3)) * (BKS * 2))
        + (uint32_t)(((lane >> 4) << 3) * 2);
    const uint32_t bAddr = Bbase
        + (uint32_t)(((lane & 7) + ((lane >> 4) << 3)) * (BKS * 2))
        + (uint32_t)(((lane >> 3) & 1) << 4);

    for (int tile = blockIdx.x; tile < N_TILES_P; tile += GRID_P) {
        int b  = tile / (NN / 128);
        int n0 = (tile % (NN / 128)) * 128;
        const float* pclb = pcl + ((size_t)b * NN + n0) * 3;
        float* outb = out + ((size_t)b * NN + n0) * 3;

        for (int i = t; i < 128 * 3; i += 256) outb[i] = pclb[i];

        // h1 = relu(pcl @ Wf1 + bf1) -> A_s bf16
        {
            int r = t & 127, half = t >> 7;
            float x0 = pclb[r * 3 + 0], x1 = pclb[r * 3 + 1], x2 = pclb[r * 3 + 2];
#pragma unroll 8
            for (int j = half * 64; j < half * 64 + 64; j += 2) {
                float v0 = fmaf(x0, shWf1[j],     fmaf(x1, shWf1[128 + j],     fmaf(x2, shWf1[256 + j],     shbf1[j])));
                float v1 = fmaf(x0, shWf1[j + 1], fmaf(x1, shWf1[128 + j + 1], fmaf(x2, shWf1[256 + j + 1], shbf1[j + 1])));
                *(__nv_bfloat162*)(A_s + r * (BKS * 2) + j * 2) =
                    __floats2bfloat162_rn(fmaxf(v0, 0.f), fmaxf(v1, 0.f));
            }
        }
        __syncthreads();

        float acc[16][4];

        // GEMM1: feat = h1 @ Wf2 + bf2 (no relu) -> A_s bf16
        warp_gemm(aAddr, bAddr, acc);
        __syncthreads();
#pragma unroll
        for (int j = 0; j < 16; ++j) {
            int c = j * 8 + cpos;
            float b0v = shbf2[c], b1v = shbf2[c + 1];
            *(__nv_bfloat162*)(A_s + (mrow + rgrp) * (BKS * 2) + c * 2) =
                __floats2bfloat162_rn(acc[j][0] + b0v, acc[j][1] + b1v);
            *(__nv_bfloat162*)(A_s + (mrow + rgrp + 8) * (BKS * 2) + c * 2) =
                __floats2bfloat162_rn(acc[j][2] + b0v, acc[j][3] + b1v);
        }
        __syncthreads();

        // GEMM2: gW0 = feat @ W0[3:] + b0 -> global fp32
        warp_gemm(aAddr, bAddr + (uint32_t)A_BYTES, acc);
        {
            float* gb = g_gW0 + ((size_t)b * NN + n0) * 128;
#pragma unroll
            for (int j = 0; j < 16; ++j) {
                int c = j * 8 + cpos;
                float b0v = shb0[c], b1v = shb0[c + 1];
                *(float2*)(gb + (size_t)(mrow + rgrp) * 128 + c) =
                    make_float2(acc[j][0] + b0v, acc[j][1] + b1v);
                *(float2*)(gb + (size_t)(mrow + rgrp + 8) * 128 + c) =
                    make_float2(acc[j][2] + b0v, acc[j][3] + b1v);
            }
        }
        __syncthreads();
    }
}

// ================= grad kernel: persistent mma.sync bf16, 2 CTAs/SM =================
__global__ __launch_bounds__(256, 2)
void grad_kernel_mma(const float* __restrict__ pcl_noisy, const float* __restrict__ pcl_cur,
                     const float* __restrict__ W0, const float* __restrict__ bb,
                     const float* __restrict__ Wo, const float* __restrict__ bo)
{
    extern __shared__ __align__(256) char smc[];
    const int t    = threadIdx.x;
    const int lane = t & 31;
    const int w    = t >> 5;

    char* A_s = smc;
    char* B_s = smc + A_BYTES;
    float* shW0 = (float*)(smc + A_BYTES + B_BYTES);
    float* shWo = shW0 + 384;
    float* shBB = shWo + 384;

    for (int i = t; i < 384; i += 256) { shW0[i] = W0[i]; shWo[i] = Wo[i]; }
    if (t < 256) shBB[t] = bb[t];
    {
        const uint4* src = (const uint4*)g_Wb;
        uint4* dst = (uint4*)B_s;
        for (int i = t; i < B_BYTES / 16; i += 256) dst[i] = src[i];
    }
    __syncthreads();

    const uint32_t Abase = smem_u32(A_s);
    const uint32_t Bbase = smem_u32(B_s);
    const int mrow = w * 16;
    const int rgrp = lane >> 2;
    const int cpos = (lane & 3) * 2;
    const uint32_t aAddr = Abase
        + (uint32_t)((mrow + (lane & 7) + (((lane >> 3) & 1) << 3)) * (BKS * 2))
        + (uint32_t)(((lane >> 4) << 3) * 2);
    const uint32_t bAddr = Bbase
        + (uint32_t)(((lane & 7) + ((lane >> 4) << 3)) * (BKS * 2))
        + (uint32_t)(((lane >> 3) & 1) << 4);

    const float bo0 = bo[0], bo1 = bo[1], bo2 = bo[2];

    for (int tile = blockIdx.x; tile < N_TILES_G; tile += GRID_P) {
        int b  = tile >> 9;
        int n0 = (tile & 511) * 32;

        // h0 = relu(centered @ W0[:3] + gW0) -> A_s bf16 (unroll 8 for LDG MLP)
        {
            int r = t & 127, half = t >> 7;
            int p = r >> 2, q = r & 3;
            int n = n0 + p;
            int m = n + q - 2;
            m = m < 0 ? 0 : (m > NN - 1 ? NN - 1 : m);
            const float* pc = pcl_cur   + ((size_t)b * NN + m) * 3;
            const float* pn = pcl_noisy + ((size_t)b * NN + n) * 3;
            float c0 = pc[0] - pn[0], c1 = pc[1] - pn[1], c2 = pc[2] - pn[2];
            const float* gw = g_gW0 + ((size_t)b * NN + n) * 128;
#pragma unroll 8
            for (int j = half * 64; j < half * 64 + 64; j += 2) {
                float2 g2 = *(const float2*)(gw + j);
                float v0 = fmaf(c0, shW0[j],     fmaf(c1, shW0[128 + j],     fmaf(c2, shW0[256 + j],     g2.x)));
                float v1 = fmaf(c0, shW0[j + 1], fmaf(c1, shW0[128 + j + 1], fmaf(c2, shW0[256 + j + 1], g2.y)));
                *(__nv_bfloat162*)(A_s + r * (BKS * 2) + j * 2) =
                    __floats2bfloat162_rn(fmaxf(v0, 0.f), fmaxf(v1, 0.f));
            }
        }
        __syncthreads();

        // fp32 h fragment copy
        float h[16][4];
#pragma unroll
        for (int j = 0; j < 16; ++j) {
            int c = j * 8 + cpos;
            float2 p0 = __bfloat1622float2(*(__nv_bfloat162*)(A_s + (mrow + rgrp) * (BKS * 2) + c * 2));
            float2 p1 = __bfloat1622float2(*(__nv_bfloat162*)(A_s + (mrow + rgrp + 8) * (BKS * 2) + c * 2));
            h[j][0] = p0.x; h[j][1] = p0.y; h[j][2] = p1.x; h[j][3] = p1.y;
        }

        float acc[16][4];

        // residual block 0
        warp_gemm(aAddr, bAddr, acc);
        __syncthreads();
#pragma unroll
        for (int j = 0; j < 16; ++j) {
            int c = j * 8 + cpos;
            float b0v = shBB[c], b1v = shBB[c + 1];
            h[j][0] += fmaxf(acc[j][0] + b0v, 0.f);
            h[j][1] += fmaxf(acc[j][1] + b1v, 0.f);
            h[j][2] += fmaxf(acc[j][2] + b0v, 0.f);
            h[j][3] += fmaxf(acc[j][3] + b1v, 0.f);
            *(__nv_bfloat162*)(A_s + (mrow + rgrp) * (BKS * 2) + c * 2) =
                __floats2bfloat162_rn(h[j][0], h[j][1]);
            *(__nv_bfloat162*)(A_s + (mrow + rgrp + 8) * (BKS * 2) + c * 2) =
                __floats2bfloat162_rn(h[j][2], h[j][3]);
        }
        __syncthreads();

        // residual block 1 (regs only)
        warp_gemm(aAddr, bAddr + (uint32_t)(128 * BKS * 2), acc);
        __syncthreads();
#pragma unroll
        for (int j = 0; j < 16; ++j) {
            int c = j * 8 + cpos;
            float b0v = shBB[128 + c], b1v = shBB[128 + c + 1];
            h[j][0] += fmaxf(acc[j][0] + b0v, 0.f);
            h[j][1] += fmaxf(acc[j][1] + b1v, 0.f);
            h[j][2] += fmaxf(acc[j][2] + b0v, 0.f);
            h[j][3] += fmaxf(acc[j][3] + b1v, 0.f);
        }

        // grad = h @ Wo + bo, reduce over 4 lanes
        {
            float g0[3] = {0.f, 0.f, 0.f}, g1[3] = {0.f, 0.f, 0.f};
#pragma unroll
            for (int j = 0; j < 16; ++j) {
                int c = j * 8 + cpos;
#pragma unroll
                for (int d = 0; d < 3; ++d) {
                    float w0v = shWo[c * 3 + d], w1v = shWo[(c + 1) * 3 + d];
                    g0[d] = fmaf(h[j][0], w0v, fmaf(h[j][1], w1v, g0[d]));
                    g1[d] = fmaf(h[j][2], w0v, fmaf(h[j][3], w1v, g1[d]));
                }
            }
#pragma unroll
            for (int d = 0; d < 3; ++d) {
                g0[d] += __shfl_xor_sync(0xffffffffu, g0[d], 1);
                g0[d] += __shfl_xor_sync(0xffffffffu, g0[d], 2);
                g1[d] += __shfl_xor_sync(0xffffffffu, g1[d], 1);
                g1[d] += __shfl_xor_sync(0xffffffffu, g1[d], 2);
            }
            if ((lane & 3) == 0) {
                int r = mrow + rgrp;
                float* gp0 = g_grad + (((size_t)b * NN + n0) * 4 + r) * 3;
                float* gp1 = g_grad + (((size_t)b * NN + n0) * 4 + r + 8) * 3;
                gp0[0] = g0[0] + bo0; gp0[1] = g0[1] + bo1; gp0[2] = g0[2] + bo2;
                gp1[0] = g1[0] + bo0; gp1[1] = g1[1] + bo1; gp1[2] = g1[2] + bo2;
            }
        }
    }
}

// ================= gather + update =================
__global__ void gather_kernel(float* __restrict__ pcl, float s)
{
    int idx = blockIdx.x * blockDim.x + threadIdx.x;
    if (idx >= BN * NN) return;
    int b = idx / NN, m = idx - b * NN;
    const float* G = g_grad + (size_t)b * NN * 12;

    float a0 = 0.f, a1 = 0.f, a2 = 0.f;
#pragma unroll
    for (int k = 0; k < 4; ++k) {
        int n = m + 2 - k;
        if (n >= 0 && n < NN) {
            const float* g = G + ((size_t)n * 4 + k) * 3;
            a0 += g[0]; a1 += g[1]; a2 += g[2];
        }
    }
    if (m == 0) {
        a0 += G[0] + G[3] + G[12];
        a1 += G[1] + G[4] + G[13];
        a2 += G[2] + G[5] + G[14];
    }
    if (m == NN - 1) {
        const float* g = G + (((size_t)(NN - 1)) * 4 + 3) * 3;
        a0 += g[0]; a1 += g[1]; a2 += g[2];
    }
    float* p = pcl + (size_t)idx * 3;
    p[0] += s * a0; p[1] += s * a1; p[2] += s * a2;
}

// ================= launch =================
extern "C" void kernel_launch(void* const* d_in, const int* in_sizes, int n_in,
                              void* d_out, int out_size)
{
    const float* pcl = (const float*)d_in[0];
    const float* Wf1 = (const float*)d_in[1];
    const float* bf1 = (const float*)d_in[2];
    const float* Wf2 = (const float*)d_in[3];
    const float* bf2 = (const float*)d_in[4];
    const float* W0  = (const float*)d_in[5];
    const float* b0  = (const float*)d_in[6];
    const float* Wb  = (const float*)d_in[7];
    const float* bb  = (const float*)d_in[8];
    const float* Wo  = (const float*)d_in[9];
    const float* bo  = (const float*)d_in[10];
    float* out = (float*)d_out;

    cudaFuncSetAttribute(precompute_mma, cudaFuncAttributeMaxDynamicSharedMemorySize, GK_SMEM);
    cudaFuncSetAttribute(grad_kernel_mma, cudaFuncAttributeMaxDynamicSharedMemorySize, GK_SMEM);

    convert_w_kernel<<<(4 * 128 * 128 + 255) / 256, 256>>>(Wb, Wf2, W0);
    precompute_mma<<<GRID_P, 256, GK_SMEM>>>(pcl, Wf1, bf1, bf2, b0, out);

    float s = 0.2f;
    for (int step = 0; step < 4; ++step) {
        grad_kernel_mma<<<GRID_P, 256, GK_SMEM>>>(pcl, out, W0, bb, Wo, bo);
        gather_kernel<<<(BN * NN + 255) / 256, 256>>>(out, s);
        s *= 0.95f;
    }
}